// round 1
// baseline (speedup 1.0000x reference)
#include <cuda_runtime.h>
#include <cstdint>
#include <math.h>

#define NN 16
#define TT 800
#define FF 90
#define SS 128
#define LL 200
#define NEGF (-1e30f)

// per-utterance scores scratch (device globals: no allocation allowed)
__device__ float g_den[NN];
__device__ float g_num[NN];

// ---- packed fp32x2 helpers (sm_103a) ----
__device__ __forceinline__ unsigned long long fma_f32x2(unsigned long long a,
                                                        unsigned long long b,
                                                        unsigned long long c) {
    unsigned long long d;
    asm("fma.rn.f32x2 %0, %1, %2, %3;" : "=l"(d) : "l"(a), "l"(b), "l"(c));
    return d;
}
__device__ __forceinline__ unsigned long long add_f32x2(unsigned long long a,
                                                        unsigned long long b) {
    unsigned long long d;
    asm("add.rn.f32x2 %0, %1, %2;" : "=l"(d) : "l"(a), "l"(b));
    return d;
}
__device__ __forceinline__ unsigned long long pack2(float lo, float hi) {
    unsigned long long d;
    asm("mov.b64 %0, {%1, %2};" : "=l"(d) : "f"(lo), "f"(hi));
    return d;
}
__device__ __forceinline__ float2 unpack2(unsigned long long v) {
    float lo, hi;
    asm("mov.b64 {%0, %1}, %2;" : "=f"(lo), "=f"(hi) : "l"(v));
    return make_float2(lo, hi);
}

__global__ __launch_bounds__(256, 1)
void mmi_forward(const float* __restrict__ nnet,   // [N, T, F] log-softmax
                 const int*   __restrict__ sup,    // [N, 3]
                 const float* __restrict__ trans,  // [S, S]
                 const int*   __restrict__ dlab,   // [S]
                 const int*   __restrict__ nlab,   // [N, L]
                 const int*   __restrict__ nlens)  // [N]
{
    __shared__ __align__(16) float sh_v[2][SS];
    __shared__ unsigned sh_wmax[2][4];
    __shared__ float sh_wsum[4];
    __shared__ float sh_a[2][LL + 8];

    const int tid = threadIdx.x;
    const int b   = blockIdx.x;

    if (b < NN) {
        // ================= denominator forward (scaled linear space) ==========
        const int n  = b;
        const int nf = sup[n * 3 + 2];

        // thread s owns output state s; E column in registers, packed as f32x2
        unsigned long long E2[SS / 2];
        const float* lp_base = nnet;  // dummy init
        float lp = 0.f;

        if (tid < SS) {
            const int s = tid;
            #pragma unroll
            for (int k = 0; k < SS / 2; ++k) {
                float e0 = expf(trans[(2 * k)     * SS + s]);
                float e1 = expf(trans[(2 * k + 1) * SS + s]);
                E2[k] = pack2(e0, e1);
            }
            const int lab = dlab[s];
            lp_base = nnet + (long long)n * TT * FF + lab;
            lp = __ldg(lp_base);                       // log-prob for t=0
            sh_v[0][s] = (s == 0) ? 1.0f : 0.0f;       // exp(alpha0)
        }
        __syncthreads();

        int cur = 0;
        float scale = 1.0f;     // 2^{-e_prev}, exact power of two
        long long Mexp = 0;     // accumulated exponents
        int lastE = 0;

        for (int t = 0; t < nf; ++t) {
            if (tid < SS) {
                const float p = expf(lp);
                const int tn = (t + 1 < TT) ? (t + 1) : (TT - 1);
                const float lpn = __ldg(lp_base + (long long)tn * FF);  // prefetch

                const ulonglong2* vp =
                    reinterpret_cast<const ulonglong2*>(&sh_v[cur][0]);
                unsigned long long a0 = 0ull, a1 = 0ull, a2 = 0ull, a3 = 0ull;
                #pragma unroll
                for (int i = 0; i < SS / 4; ++i) {
                    ulonglong2 q = vp[i];   // broadcast LDS.128: v[4i..4i+3]
                    if (i & 1) {
                        a2 = fma_f32x2(q.x, E2[2 * i],     a2);
                        a3 = fma_f32x2(q.y, E2[2 * i + 1], a3);
                    } else {
                        a0 = fma_f32x2(q.x, E2[2 * i],     a0);
                        a1 = fma_f32x2(q.y, E2[2 * i + 1], a1);
                    }
                }
                a0 = add_f32x2(a0, a2);
                a1 = add_f32x2(a1, a3);
                a0 = add_f32x2(a0, a1);
                const float2 u = unpack2(a0);
                const float dot = u.x + u.y;

                const float accv = dot * (p * scale);   // apply emit + prev scale
                // warp max of positive floats via int compare
                const unsigned wm =
                    __reduce_max_sync(0xffffffffu, __float_as_uint(accv));
                if ((tid & 31) == 0) sh_wmax[cur][tid >> 5] = wm;
                sh_v[cur ^ 1][tid] = accv;
                lp = lpn;
            }
            __syncthreads();
            if (tid < SS) {
                unsigned m0 = sh_wmax[cur][0];
                m0 = max(m0, sh_wmax[cur][1]);
                m0 = max(m0, sh_wmax[cur][2]);
                m0 = max(m0, sh_wmax[cur][3]);
                const int e = (int)(m0 >> 23) - 127;   // ilogb(max)
                lastE = e;
                Mexp += e;
                scale = __uint_as_float((unsigned)(127 - e) << 23);  // exact 2^-e
            }
            cur ^= 1;
        }

        // den_score = C*ln2 + log(sum v), where C excludes the final (unapplied) e
        if (tid < SS) {
            float v = sh_v[cur][tid];
            #pragma unroll
            for (int o = 16; o; o >>= 1) v += __shfl_xor_sync(0xffffffffu, v, o);
            if ((tid & 31) == 0) sh_wsum[tid >> 5] = v;
        }
        __syncthreads();
        if (tid == 0) {
            const float s = sh_wsum[0] + sh_wsum[1] + sh_wsum[2] + sh_wsum[3];
            const double den = (double)(Mexp - (long long)lastE) * 0.6931471805599453
                             + (double)logf(s);
            g_den[n] = (float)den;
        }
    } else {
        // ================= numerator forward (log space) =======================
        const int n  = b - NN;
        const int nf = sup[n * 3 + 2];
        const int qi = nlens[n];

        const float* lp_base = nnet;  // dummy init
        float lp = 0.f;
        const int l = tid + 1;        // thread tid computes state l = tid+1

        if (tid < LL) {
            const int lab = nlab[n * LL + tid];   // label for transition into l
            lp_base = nnet + (long long)n * TT * FF + lab;
            lp = __ldg(lp_base);
        }
        if (tid <= LL) {
            sh_a[0][tid] = (tid == 0) ? 0.0f : NEGF;
            sh_a[1][tid] = NEGF;
        }
        int cur = 0;
        __syncthreads();

        for (int t = 0; t < nf; ++t) {
            if (tid < LL) {
                const float x = sh_a[cur][l];
                const float y = sh_a[cur][l - 1];
                const float hi = fmaxf(x, y);
                const float lo = fminf(x, y);
                const float nv = hi + log1pf(expf(lo - hi)) + lp;

                const int tn = (t + 1 < TT) ? (t + 1) : (TT - 1);
                const float lpn = __ldg(lp_base + (long long)tn * FF);

                sh_a[cur ^ 1][l] = nv;
                if (tid == 0) sh_a[cur ^ 1][0] = NEGF;
                lp = lpn;
            }
            __syncthreads();
            cur ^= 1;
        }
        if (tid == 0) g_num[n] = sh_a[cur][qi];
    }
}

__global__ void mmi_finalize(const int* __restrict__ sup, float* __restrict__ out)
{
    const int tid = threadIdx.x;  // 32 threads
    float tot = 0.f, fr = 0.f, af = 0.f;
    if (tid < NN) {
        const int nf = sup[tid * 3 + 2];
        const float t = g_num[tid] - g_den[tid];
        const bool fin = isfinite(t) && (t > 0.5f * NEGF);
        tot = fin ? t : 0.f;
        fr  = fin ? (float)nf : 0.f;
        af  = (float)nf;
    }
    #pragma unroll
    for (int o = 16; o; o >>= 1) {
        tot += __shfl_xor_sync(0xffffffffu, tot, o);
        fr  += __shfl_xor_sync(0xffffffffu, fr, o);
        af  += __shfl_xor_sync(0xffffffffu, af, o);
    }
    if (tid == 0) {
        out[0] = tot;
        out[1] = fr;
        out[2] = af;
    }
}

extern "C" void kernel_launch(void* const* d_in, const int* in_sizes, int n_in,
                              void* d_out, int out_size)
{
    const float* nnet  = (const float*)d_in[0];
    const int*   sup   = (const int*)  d_in[1];
    const float* trans = (const float*)d_in[2];
    const int*   dlab  = (const int*)  d_in[3];
    const int*   nlab  = (const int*)  d_in[4];
    const int*   nlens = (const int*)  d_in[5];

    mmi_forward<<<2 * NN, 256>>>(nnet, sup, trans, dlab, nlab, nlens);
    mmi_finalize<<<1, 32>>>(sup, (float*)d_out);
}

// round 3
// speedup vs baseline: 1.1739x; 1.1739x over previous
#include <cuda_runtime.h>
#include <cstdint>
#include <math.h>

#define NN 16
#define TT 800
#define FF 90
#define SS 128
#define LL 200
#define NEGF (-1e30f)

// per-utterance scores scratch (device globals: no allocation allowed)
__device__ float g_den[NN];
__device__ float g_num[NN];

// ---- packed fp32x2 helpers (sm_103a) ----
__device__ __forceinline__ unsigned long long fma_f32x2(unsigned long long a,
                                                        unsigned long long b,
                                                        unsigned long long c) {
    unsigned long long d;
    asm("fma.rn.f32x2 %0, %1, %2, %3;" : "=l"(d) : "l"(a), "l"(b), "l"(c));
    return d;
}
__device__ __forceinline__ unsigned long long add_f32x2(unsigned long long a,
                                                        unsigned long long b) {
    unsigned long long d;
    asm("add.rn.f32x2 %0, %1, %2;" : "=l"(d) : "l"(a), "l"(b));
    return d;
}
__device__ __forceinline__ unsigned long long pack2(float lo, float hi) {
    unsigned long long d;
    asm("mov.b64 %0, {%1, %2};" : "=l"(d) : "f"(lo), "f"(hi));
    return d;
}
__device__ __forceinline__ float2 unpack2(unsigned long long v) {
    float lo, hi;
    asm("mov.b64 {%0, %1}, %2;" : "=f"(lo), "=f"(hi) : "l"(v));
    return make_float2(lo, hi);
}

__global__ __launch_bounds__(256, 1)
void mmi_forward(const float* __restrict__ nnet,   // [N, T, F] log-softmax
                 const int*   __restrict__ sup,    // [N, 3]
                 const float* __restrict__ trans,  // [S, S]
                 const int*   __restrict__ dlab,   // [S]
                 const int*   __restrict__ nlab,   // [N, L]
                 const int*   __restrict__ nlens)  // [N]
{
    // den: v stored as two 64-float halves at offsets 0 and 68 (16B skew ->
    // even/odd-lane broadcast LDS.128 hit disjoint banks)
    __shared__ __align__(16) float sh_v[2][136];
    __shared__ float sh_wsum[4];
    __shared__ float sh_a[2][LL + 8];

    const int tid = threadIdx.x;
    const int b   = blockIdx.x;

    if (b < NN) {
        // ============ denominator forward (scaled linear space) ==============
        const int n  = b;
        const int nf = sup[n * 3 + 2];

        const int s    = tid >> 1;          // output state (2 threads per state)
        const int kh   = tid & 1;           // K half: [kh*64, kh*64+64)
        const int sidx = (s < 64) ? s : s + 4;   // padded storage index

        // E column half in registers, packed as f32x2 (64 regs)
        unsigned long long E2[32];
        #pragma unroll 8
        for (int j = 0; j < 32; ++j) {
            const int k = kh * 64 + 2 * j;
            E2[j] = pack2(expf(trans[k * SS + s]),
                          expf(trans[(k + 1) * SS + s]));
        }
        const int lab = dlab[s];
        const float* lp_base = nnet + (long long)n * TT * FF + lab;
        float lp  = __ldg(lp_base);                          // t = 0
        float lp1 = __ldg(lp_base + FF);                     // t = 1

        if (tid < 128) sh_v[0][(tid < 64) ? tid : tid + 4] = (tid == 0) ? 1.0f : 0.0f;
        __syncthreads();

        int cur  = 0;
        int Mexp = 0;

        for (int t = 0; t < nf; ++t) {
            // exact 2^-e rescale keyed to v[0]'s exponent (uniform across block)
            const float v0 = sh_v[cur][0];
            const int   eb = (int)(__float_as_uint(v0) >> 23);      // biased exp
            const float scale = __uint_as_float((unsigned)(254 - eb) << 23);
            Mexp += eb - 127;
            const float ps = __expf(lp) * scale;

            const int   tn   = (t + 2 < TT) ? (t + 2) : (TT - 1);
            const float lpn2 = __ldg(lp_base + (long long)tn * FF); // prefetch d=2

            // batch-load this thread's 64-float v half into registers
            const ulonglong2* vp =
                reinterpret_cast<const ulonglong2*>(&sh_v[cur][kh * 68]);
            ulonglong2 q[16];
            #pragma unroll
            for (int i = 0; i < 16; ++i) q[i] = vp[i];

            unsigned long long a0 = 0ull, a1 = 0ull, a2 = 0ull, a3 = 0ull;
            #pragma unroll
            for (int i = 0; i < 4; ++i) {
                a0 = fma_f32x2(q[4 * i + 0].x, E2[8 * i + 0], a0);
                a1 = fma_f32x2(q[4 * i + 0].y, E2[8 * i + 1], a1);
                a2 = fma_f32x2(q[4 * i + 1].x, E2[8 * i + 2], a2);
                a3 = fma_f32x2(q[4 * i + 1].y, E2[8 * i + 3], a3);
                a0 = fma_f32x2(q[4 * i + 2].x, E2[8 * i + 4], a0);
                a1 = fma_f32x2(q[4 * i + 2].y, E2[8 * i + 5], a1);
                a2 = fma_f32x2(q[4 * i + 3].x, E2[8 * i + 6], a2);
                a3 = fma_f32x2(q[4 * i + 3].y, E2[8 * i + 7], a3);
            }
            a0 = add_f32x2(a0, a2);
            a1 = add_f32x2(a1, a3);
            a0 = add_f32x2(a0, a1);
            const float2 u = unpack2(a0);
            float dot = u.x + u.y;
            dot += __shfl_xor_sync(0xffffffffu, dot, 1);   // combine K halves

            const float accv = dot * ps;
            if (!kh) sh_v[cur ^ 1][sidx] = accv;
            lp  = lp1;
            lp1 = lpn2;
            __syncthreads();
            cur ^= 1;
        }

        // den = Mexp*ln2 + log(sum v)
        if (tid < 128) {
            float v = sh_v[cur][(tid < 64) ? tid : tid + 4];
            #pragma unroll
            for (int o = 16; o; o >>= 1) v += __shfl_xor_sync(0xffffffffu, v, o);
            if ((tid & 31) == 0) sh_wsum[tid >> 5] = v;
        }
        __syncthreads();
        if (tid == 0) {
            const float sv = sh_wsum[0] + sh_wsum[1] + sh_wsum[2] + sh_wsum[3];
            g_den[n] = (float)((double)Mexp * 0.6931471805599453 + (double)logf(sv));
        }
    } else {
        // ============ numerator forward (log space) ===========================
        const int n  = b - NN;
        const int nf = sup[n * 3 + 2];
        const int qi = nlens[n];

        const float* lp_base = nnet;  // dummy init
        float lp = 0.f, lp1 = 0.f;
        const int l = tid + 1;        // thread tid computes state l = tid+1

        if (tid < LL) {
            const int lab = nlab[n * LL + tid];
            lp_base = nnet + (long long)n * TT * FF + lab;
            lp  = __ldg(lp_base);
            lp1 = __ldg(lp_base + FF);
        }
        if (tid <= LL) {
            sh_a[0][tid] = (tid == 0) ? 0.0f : NEGF;
            sh_a[1][tid] = NEGF;
        }
        int cur = 0;
        __syncthreads();

        for (int t = 0; t < nf; ++t) {
            if (tid < LL) {
                const float x  = sh_a[cur][l];
                const float y  = sh_a[cur][l - 1];
                const float hi = fmaxf(x, y);
                const float lo = fminf(x, y);
                const float nv = hi + __logf(1.0f + __expf(lo - hi)) + lp;

                const int   tn   = (t + 2 < TT) ? (t + 2) : (TT - 1);
                const float lpn2 = __ldg(lp_base + (long long)tn * FF);

                sh_a[cur ^ 1][l] = nv;
                if (tid == 0) sh_a[cur ^ 1][0] = NEGF;   // alpha[0] = NEG every step
                lp  = lp1;
                lp1 = lpn2;
            }
            __syncthreads();
            cur ^= 1;
        }
        if (tid == 0) g_num[n] = sh_a[cur][qi];
    }
}

__global__ void mmi_finalize(const int* __restrict__ sup, float* __restrict__ out)
{
    const int tid = threadIdx.x;  // 32 threads
    float tot = 0.f, fr = 0.f, af = 0.f;
    if (tid < NN) {
        const int nf = sup[tid * 3 + 2];
        const float t = g_num[tid] - g_den[tid];
        const bool fin = isfinite(t) && (t > 0.5f * NEGF);
        tot = fin ? t : 0.f;
        fr  = fin ? (float)nf : 0.f;
        af  = (float)nf;
    }
    #pragma unroll
    for (int o = 16; o; o >>= 1) {
        tot += __shfl_xor_sync(0xffffffffu, tot, o);
        fr  += __shfl_xor_sync(0xffffffffu, fr, o);
        af  += __shfl_xor_sync(0xffffffffu, af, o);
    }
    if (tid == 0) {
        out[0] = tot;
        out[1] = fr;
        out[2] = af;
    }
}

extern "C" void kernel_launch(void* const* d_in, const int* in_sizes, int n_in,
                              void* d_out, int out_size)
{
    const float* nnet  = (const float*)d_in[0];
    const int*   sup   = (const int*)  d_in[1];
    const float* trans = (const float*)d_in[2];
    const int*   dlab  = (const int*)  d_in[3];
    const int*   nlab  = (const int*)  d_in[4];
    const int*   nlens = (const int*)  d_in[5];

    mmi_forward<<<2 * NN, 256>>>(nnet, sup, trans, dlab, nlab, nlens);
    mmi_finalize<<<1, 32>>>(sup, (float*)d_out);
}